// round 5
// baseline (speedup 1.0000x reference)
#include <cuda_runtime.h>
#include <math.h>

#define NN 50000
#define EE 600000
#define TOTE (EE + NN)
#define DIM 128

// packed f32x2 helpers (sm_100+ FFMA2 — ptxas never auto-fuses, PTX only)
#define PACK2(out, lo, hi) \
    asm("mov.b64 %0, {%1, %2};" : "=l"(out) : "f"(lo), "f"(hi))
#define UNPACK2(lo, hi, in) \
    asm("mov.b64 {%0, %1}, %2;" : "=f"(lo), "=f"(hi) : "l"(in))
#define FMA2(d, a, b, c) \
    asm("fma.rn.f32x2 %0, %1, %2, %3;" : "=l"(d) : "l"(a), "l"(b), "l"(c))

// ---------------- scratch (static __device__, no allocation) ----------------
__device__ int   g_is64;
__device__ int   g_deg[NN];
__device__ int   g_rowptr[NN + 1];
__device__ int   g_cursor[NN];
__device__ int   g_srcd[TOTE];
__device__ int   g_dstd[TOTE];
__device__ int   g_col[TOTE];
__device__ float g_h1[NN * DIM];
__device__ float g_als1[NN * 4];
__device__ float g_ald1[NN * 4];
__device__ float g_z[NN * DIM];     // layer-1 output after elu
__device__ float g_h2[NN * DIM];
__device__ float g_als2[NN];
__device__ float g_ald2[NN];

// ---------------- dtype detect: int64 edge_index has zero high words --------
__global__ void k_detect(const unsigned int* __restrict__ w) {
    __shared__ int any;
    if (threadIdx.x == 0) any = 0;
    __syncthreads();
    // odd 32-bit words: int64 high halves (all zero, values < 50000) vs
    // int32 edge ids (random in [0,50000), overwhelmingly nonzero).
    for (int i = threadIdx.x; i < 4096; i += blockDim.x)
        if (w[2 * i + 1] != 0u) any = 1;
    __syncthreads();
    if (threadIdx.x == 0) g_is64 = (any == 0) ? 1 : 0;
}

__global__ void k_zero(int n) {
    int i = blockIdx.x * blockDim.x + threadIdx.x;
    if (i < n) g_deg[i] = 0;
}

// build src/dst arrays (with self loops appended) + degree histogram
__global__ void k_build(const void* __restrict__ ei, int E, int n) {
    int i = blockIdx.x * blockDim.x + threadIdx.x;
    int tot = E + n;
    if (i >= tot) return;
    int s, d;
    if (i < E) {
        if (g_is64) {
            const long long* p = (const long long*)ei;
            s = (int)__ldg(&p[i]);
            d = (int)__ldg(&p[E + i]);
        } else {
            const int* p = (const int*)ei;
            s = __ldg(&p[i]);
            d = __ldg(&p[E + i]);
        }
    } else {
        s = d = i - E;  // self loop
    }
    g_srcd[i] = s;
    g_dstd[i] = d;
    atomicAdd(&g_deg[d], 1);
}

// single-block exclusive scan of degrees -> rowptr, cursor
__global__ void k_scan(int n) {
    __shared__ int buf[1024];
    int tid = threadIdx.x;
    int chunk = (n + 1023) >> 10;
    int s0 = tid * chunk;
    int s1 = min(s0 + chunk, n);
    int s = 0;
    for (int i = s0; i < s1; i++) s += g_deg[i];
    buf[tid] = s;
    __syncthreads();
    for (int d = 1; d < 1024; d <<= 1) {
        int v = buf[tid];
        int add = (tid >= d) ? buf[tid - d] : 0;
        __syncthreads();
        buf[tid] = v + add;
        __syncthreads();
    }
    int run = buf[tid] - s;  // exclusive
    for (int i = s0; i < s1; i++) {
        g_rowptr[i] = run;
        g_cursor[i] = run;
        run += g_deg[i];
    }
    if (tid == 1023) g_rowptr[n] = buf[1023];
}

__global__ void k_scatter(int tot) {
    int i = blockIdx.x * blockDim.x + threadIdx.x;
    if (i >= tot) return;
    int d = g_dstd[i];
    int p = atomicAdd(&g_cursor[d], 1);
    g_col[p] = g_srcd[i];
}

// ---------------- fused GEMM + attention dot products -----------------------
// H = X @ W  (n x 128 @ 128 x 128), plus als[n][heads], ald[n][heads]
// block = 128 threads (4 warps), 16 rows per block, warp owns 4 rows,
// lane owns 4 consecutive columns (cols 4*lane .. 4*lane+3).
// Inner loop uses packed fma.rn.f32x2 (FFMA2): 8 FFMA2 + 4 packs per k-step
// instead of 16 scalar FFMA -> ~half the FMA-pipe issue slots.
__global__ void k_gemm(const float* __restrict__ Xext,
                       const float* __restrict__ W,
                       const float* __restrict__ asrc,
                       const float* __restrict__ adst,
                       int heads, int layer, int n) {
    __shared__ float xs[16][DIM];
    const float* X = (layer == 1) ? Xext : g_z;
    float* H       = (layer == 1) ? g_h1 : g_h2;
    float* als     = (layer == 1) ? g_als1 : g_als2;
    float* ald     = (layer == 1) ? g_ald1 : g_ald2;

    int row0 = blockIdx.x * 16;
    int tid = threadIdx.x;

    // load x tile (16x128 floats = 512 float4)
    const float4* Xv = (const float4*)X;
    float4* xsv = (float4*)xs;
    for (int i = tid; i < 512; i += 128) {
        int r = i >> 5;           // row within tile
        int c = i & 31;           // float4 within row
        float4 v = make_float4(0.f, 0.f, 0.f, 0.f);
        if (row0 + r < n) v = Xv[(row0 + r) * 32 + c];
        xsv[i] = v;
    }
    __syncthreads();

    int warp = tid >> 5, lane = tid & 31;
    int r0 = warp * 4;

    unsigned long long accA[4], accB[4];   // accA = cols (x,y), accB = cols (z,w)
#pragma unroll
    for (int r = 0; r < 4; r++) { accA[r] = 0ull; accB[r] = 0ull; }  // (0.f,0.f)

    const float4* Wv = (const float4*)W;
#pragma unroll 4
    for (int k = 0; k < DIM; k++) {
        float4 w = Wv[k * 32 + lane];
        unsigned long long w01, w23;
        PACK2(w01, w.x, w.y);
        PACK2(w23, w.z, w.w);
#pragma unroll
        for (int r = 0; r < 4; r++) {
            float xr = xs[r0 + r][k];
            unsigned long long xx;
            PACK2(xx, xr, xr);
            FMA2(accA[r], xx, w01, accA[r]);
            FMA2(accB[r], xx, w23, accB[r]);
        }
    }

    float4* Hv = (float4*)H;
#pragma unroll
    for (int r = 0; r < 4; r++) {
        int row = row0 + r0 + r;
        if (row >= n) continue;
        float4 a;
        UNPACK2(a.x, a.y, accA[r]);
        UNPACK2(a.z, a.w, accB[r]);
        Hv[row * 32 + lane] = a;
        float ps, pd;
        if (heads == 4) {
            int head = lane >> 3;
            int cb = (lane & 7) * 4;
            const float* as = asrc + head * 32 + cb;
            const float* ad = adst + head * 32 + cb;
            ps = a.x * as[0] + a.y * as[1] + a.z * as[2] + a.w * as[3];
            pd = a.x * ad[0] + a.y * ad[1] + a.z * ad[2] + a.w * ad[3];
            ps += __shfl_down_sync(0xFFFFFFFFu, ps, 4, 8);
            ps += __shfl_down_sync(0xFFFFFFFFu, ps, 2, 8);
            ps += __shfl_down_sync(0xFFFFFFFFu, ps, 1, 8);
            pd += __shfl_down_sync(0xFFFFFFFFu, pd, 4, 8);
            pd += __shfl_down_sync(0xFFFFFFFFu, pd, 2, 8);
            pd += __shfl_down_sync(0xFFFFFFFFu, pd, 1, 8);
            if ((lane & 7) == 0) {
                als[row * 4 + head] = ps;
                ald[row * 4 + head] = pd;
            }
        } else {
            const float4 as = ((const float4*)asrc)[lane];
            const float4 ad = ((const float4*)adst)[lane];
            ps = a.x * as.x + a.y * as.y + a.z * as.z + a.w * as.w;
            pd = a.x * ad.x + a.y * ad.y + a.z * ad.z + a.w * ad.w;
#pragma unroll
            for (int off = 16; off; off >>= 1) {
                ps += __shfl_down_sync(0xFFFFFFFFu, ps, off);
                pd += __shfl_down_sync(0xFFFFFFFFu, pd, off);
            }
            if (lane == 0) {
                als[row] = ps;
                ald[row] = pd;
            }
        }
    }
}

// ---------------- layer-1 attention aggregation (one warp per dst) ----------
// online softmax over the dst's edge list; heads=4, 32 channels each.
// lane j holds channels 4j..4j+3 -> head = j>>3.
__global__ void k_att1(const float* __restrict__ b1, int n) {
    int gw = (blockIdx.x * blockDim.x + threadIdx.x) >> 5;
    int lane = threadIdx.x & 31;
    if (gw >= n) return;
    int head = lane >> 3;
    float aldh = g_ald1[gw * 4 + head];

    float m = -1e30f, ssum = 0.f;
    float4 acc = make_float4(0.f, 0.f, 0.f, 0.f);
    int beg = g_rowptr[gw], end = g_rowptr[gw + 1];
    const float4* hv4 = (const float4*)g_h1;

    int s = (beg < end) ? __ldg(&g_col[beg]) : 0;
    for (int e = beg; e < end; e++) {
        int snext = (e + 1 < end) ? __ldg(&g_col[e + 1]) : 0;
        float ev = __ldg(&g_als1[s * 4 + head]) + aldh;
        ev = ev > 0.f ? ev : 0.2f * ev;                 // leaky relu
        float m2 = fmaxf(m, ev);
        float scale = __expf(m - m2);
        float wgt = __expf(ev - m2);
        ssum = ssum * scale + wgt;
        float4 h = __ldg(&hv4[s * 32 + lane]);
        acc.x = acc.x * scale + wgt * h.x;
        acc.y = acc.y * scale + wgt * h.y;
        acc.z = acc.z * scale + wgt * h.z;
        acc.w = acc.w * scale + wgt * h.w;
        m = m2;
        s = snext;
    }
    float inv = 1.f / (ssum + 1e-16f);
    float4 bb = ((const float4*)b1)[lane];
    float4 o;
    o.x = acc.x * inv + bb.x;
    o.y = acc.y * inv + bb.y;
    o.z = acc.z * inv + bb.z;
    o.w = acc.w * inv + bb.w;
    // elu
    o.x = o.x > 0.f ? o.x : expm1f(o.x);
    o.y = o.y > 0.f ? o.y : expm1f(o.y);
    o.z = o.z > 0.f ? o.z : expm1f(o.z);
    o.w = o.w > 0.f ? o.w : expm1f(o.w);
    ((float4*)g_z)[gw * 32 + lane] = o;
}

// ---------------- layer-2 attention aggregation (heads=1, 128 ch) ----------
__global__ void k_att2(const float* __restrict__ b2, float* __restrict__ out, int n) {
    int gw = (blockIdx.x * blockDim.x + threadIdx.x) >> 5;
    int lane = threadIdx.x & 31;
    if (gw >= n) return;
    float aldh = g_ald2[gw];

    float m = -1e30f, ssum = 0.f;
    float4 acc = make_float4(0.f, 0.f, 0.f, 0.f);
    int beg = g_rowptr[gw], end = g_rowptr[gw + 1];
    const float4* hv4 = (const float4*)g_h2;

    int s = (beg < end) ? __ldg(&g_col[beg]) : 0;
    for (int e = beg; e < end; e++) {
        int snext = (e + 1 < end) ? __ldg(&g_col[e + 1]) : 0;
        float ev = __ldg(&g_als2[s]) + aldh;
        ev = ev > 0.f ? ev : 0.2f * ev;
        float m2 = fmaxf(m, ev);
        float scale = __expf(m - m2);
        float wgt = __expf(ev - m2);
        ssum = ssum * scale + wgt;
        float4 h = __ldg(&hv4[s * 32 + lane]);
        acc.x = acc.x * scale + wgt * h.x;
        acc.y = acc.y * scale + wgt * h.y;
        acc.z = acc.z * scale + wgt * h.z;
        acc.w = acc.w * scale + wgt * h.w;
        m = m2;
        s = snext;
    }
    float inv = 1.f / (ssum + 1e-16f);
    float4 bb = ((const float4*)b2)[lane];
    float4 o;
    o.x = acc.x * inv + bb.x;
    o.y = acc.y * inv + bb.y;
    o.z = acc.z * inv + bb.z;
    o.w = acc.w * inv + bb.w;
    ((float4*)out)[gw * 32 + lane] = o;
}

// ---------------- launch -----------------------------------------------------
extern "C" void kernel_launch(void* const* d_in, const int* in_sizes, int n_in,
                              void* d_out, int out_size) {
    const float* x  = (const float*)d_in[0];
    const void*  ei = d_in[1];
    const float* W1 = (const float*)d_in[2];
    const float* as1 = (const float*)d_in[3];
    const float* ad1 = (const float*)d_in[4];
    const float* b1 = (const float*)d_in[5];
    const float* W2 = (const float*)d_in[6];
    const float* as2 = (const float*)d_in[7];
    const float* ad2 = (const float*)d_in[8];
    const float* b2 = (const float*)d_in[9];
    float* out = (float*)d_out;

    int E = in_sizes[1] / 2;
    int n = in_sizes[0] / DIM;
    int tot = E + n;

    k_detect<<<1, 256>>>((const unsigned int*)ei);
    k_zero<<<(n + 255) / 256, 256>>>(n);
    k_build<<<(tot + 255) / 256, 256>>>(ei, E, n);
    k_scan<<<1, 1024>>>(n);
    k_scatter<<<(tot + 255) / 256, 256>>>(tot);

    int gblocks = (n + 15) / 16;
    int ablocks = (n * 32 + 127) / 128;

    k_gemm<<<gblocks, 128>>>(x, W1, as1, ad1, 4, 1, n);
    k_att1<<<ablocks, 128>>>(b1, n);
    k_gemm<<<gblocks, 128>>>(x, W2, as2, ad2, 1, 2, n);
    k_att2<<<ablocks, 128>>>(b2, out, n);
}

// round 8
// speedup vs baseline: 1.2926x; 1.2926x over previous
#include <cuda_runtime.h>
#include <math.h>

#define NN 50000
#define EE 600000
#define TOTE (EE + NN)
#define DIM 128
#define SCAN_BLK 512
#define SCAN_NB ((NN + SCAN_BLK - 1) / SCAN_BLK)   // 98

// packed f32x2 helpers (sm_100+ FFMA2 — ptxas never auto-fuses, PTX only)
#define PACK2(out, lo, hi) \
    asm("mov.b64 %0, {%1, %2};" : "=l"(out) : "f"(lo), "f"(hi))
#define UNPACK2(lo, hi, in) \
    asm("mov.b64 {%0, %1}, %2;" : "=f"(lo), "=f"(hi) : "l"(in))
#define FMA2(d, a, b, c) \
    asm("fma.rn.f32x2 %0, %1, %2, %3;" : "=l"(d) : "l"(a), "l"(b), "l"(c))

// ---------------- scratch (static __device__, no allocation) ----------------
__device__ int   g_is64;
__device__ int   g_deg[NN];
__device__ int   g_rowptr[NN + 1];
__device__ int   g_cursor[NN];
__device__ int   g_srcd[TOTE];
__device__ int   g_dstd[TOTE];
__device__ int   g_col[TOTE];
__device__ int   g_bsum[256];
__device__ float g_h1[NN * DIM];
__device__ float g_als1[NN * 4];
__device__ float g_ald1[NN * 4];
__device__ float g_z[NN * DIM];     // layer-1 output after elu
__device__ float g_h2[NN * DIM];
__device__ float g_als2[NN];
__device__ float g_ald2[NN];

// ---------------- dtype detect: int64 edge_index has zero high words --------
__global__ void k_detect(const unsigned int* __restrict__ w) {
    __shared__ int any;
    if (threadIdx.x == 0) any = 0;
    __syncthreads();
    for (int i = threadIdx.x; i < 4096; i += blockDim.x)
        if (w[2 * i + 1] != 0u) any = 1;
    __syncthreads();
    if (threadIdx.x == 0) g_is64 = (any == 0) ? 1 : 0;
}

__global__ void k_zero(int n) {
    int i = blockIdx.x * blockDim.x + threadIdx.x;
    if (i < n) g_deg[i] = 0;
}

// build src/dst arrays (with self loops appended) + degree histogram
__global__ void k_build(const void* __restrict__ ei, int E, int n) {
    int i = blockIdx.x * blockDim.x + threadIdx.x;
    int tot = E + n;
    if (i >= tot) return;
    int s, d;
    if (i < E) {
        if (g_is64) {
            const long long* p = (const long long*)ei;
            s = (int)__ldg(&p[i]);
            d = (int)__ldg(&p[E + i]);
        } else {
            const int* p = (const int*)ei;
            s = __ldg(&p[i]);
            d = __ldg(&p[E + i]);
        }
    } else {
        s = d = i - E;  // self loop
    }
    g_srcd[i] = s;
    g_dstd[i] = d;
    atomicAdd(&g_deg[d], 1);
}

// ---------------- 3-phase hierarchical exclusive scan -----------------------
// phase A: per-block inclusive scan of 512 degs; write local-EXCLUSIVE value
// into rowptr, block total into g_bsum.
__global__ void k_scan_a(int n) {
    __shared__ int buf[SCAN_BLK];
    int tid = threadIdx.x;
    int i = blockIdx.x * SCAN_BLK + tid;
    int v = (i < n) ? g_deg[i] : 0;
    buf[tid] = v;
    __syncthreads();
#pragma unroll
    for (int d = 1; d < SCAN_BLK; d <<= 1) {
        int t = buf[tid];
        int add = (tid >= d) ? buf[tid - d] : 0;
        __syncthreads();
        buf[tid] = t + add;
        __syncthreads();
    }
    if (i < n) g_rowptr[i] = buf[tid] - v;   // local exclusive
    if (tid == SCAN_BLK - 1) g_bsum[blockIdx.x] = buf[tid];
}

// phase B: single block exclusive-scans the block sums; writes grand total.
__global__ void k_scan_b(int nb, int n) {
    __shared__ int buf[256];
    int tid = threadIdx.x;  // 256 threads
    int v = (tid < nb) ? g_bsum[tid] : 0;
    buf[tid] = v;
    __syncthreads();
#pragma unroll
    for (int d = 1; d < 256; d <<= 1) {
        int t = buf[tid];
        int add = (tid >= d) ? buf[tid - d] : 0;
        __syncthreads();
        buf[tid] = t + add;
        __syncthreads();
    }
    if (tid < nb) g_bsum[tid] = buf[tid] - v;   // exclusive
    if (tid == 255) g_rowptr[n] = buf[255];     // grand total
}

// phase C: add block offsets; init cursor.
__global__ void k_scan_c(int n) {
    int i = blockIdx.x * SCAN_BLK + threadIdx.x;
    if (i >= n) return;
    int r = g_rowptr[i] + g_bsum[blockIdx.x];
    g_rowptr[i] = r;
    g_cursor[i] = r;
}

__global__ void k_scatter(int tot) {
    int i = blockIdx.x * blockDim.x + threadIdx.x;
    if (i >= tot) return;
    int d = g_dstd[i];
    int p = atomicAdd(&g_cursor[d], 1);
    g_col[p] = g_srcd[i];
}

// ---------------- fused GEMM + attention dot products -----------------------
__global__ void k_gemm(const float* __restrict__ Xext,
                       const float* __restrict__ W,
                       const float* __restrict__ asrc,
                       const float* __restrict__ adst,
                       int heads, int layer, int n) {
    __shared__ float xs[16][DIM];
    const float* X = (layer == 1) ? Xext : g_z;
    float* H       = (layer == 1) ? g_h1 : g_h2;
    float* als     = (layer == 1) ? g_als1 : g_als2;
    float* ald     = (layer == 1) ? g_ald1 : g_ald2;

    int row0 = blockIdx.x * 16;
    int tid = threadIdx.x;

    const float4* Xv = (const float4*)X;
    float4* xsv = (float4*)xs;
    for (int i = tid; i < 512; i += 128) {
        int r = i >> 5;
        int c = i & 31;
        float4 v = make_float4(0.f, 0.f, 0.f, 0.f);
        if (row0 + r < n) v = Xv[(row0 + r) * 32 + c];
        xsv[i] = v;
    }
    __syncthreads();

    int warp = tid >> 5, lane = tid & 31;
    int r0 = warp * 4;

    unsigned long long accA[4], accB[4];
#pragma unroll
    for (int r = 0; r < 4; r++) { accA[r] = 0ull; accB[r] = 0ull; }

    const float4* Wv = (const float4*)W;
#pragma unroll 4
    for (int k = 0; k < DIM; k++) {
        float4 w = Wv[k * 32 + lane];
        unsigned long long w01, w23;
        PACK2(w01, w.x, w.y);
        PACK2(w23, w.z, w.w);
#pragma unroll
        for (int r = 0; r < 4; r++) {
            float xr = xs[r0 + r][k];
            unsigned long long xx;
            PACK2(xx, xr, xr);
            FMA2(accA[r], xx, w01, accA[r]);
            FMA2(accB[r], xx, w23, accB[r]);
        }
    }

    float4* Hv = (float4*)H;
#pragma unroll
    for (int r = 0; r < 4; r++) {
        int row = row0 + r0 + r;
        if (row >= n) continue;
        float4 a;
        UNPACK2(a.x, a.y, accA[r]);
        UNPACK2(a.z, a.w, accB[r]);
        Hv[row * 32 + lane] = a;
        float ps, pd;
        if (heads == 4) {
            int head = lane >> 3;
            int cb = (lane & 7) * 4;
            const float* as = asrc + head * 32 + cb;
            const float* ad = adst + head * 32 + cb;
            ps = a.x * as[0] + a.y * as[1] + a.z * as[2] + a.w * as[3];
            pd = a.x * ad[0] + a.y * ad[1] + a.z * ad[2] + a.w * ad[3];
            ps += __shfl_down_sync(0xFFFFFFFFu, ps, 4, 8);
            ps += __shfl_down_sync(0xFFFFFFFFu, ps, 2, 8);
            ps += __shfl_down_sync(0xFFFFFFFFu, ps, 1, 8);
            pd += __shfl_down_sync(0xFFFFFFFFu, pd, 4, 8);
            pd += __shfl_down_sync(0xFFFFFFFFu, pd, 2, 8);
            pd += __shfl_down_sync(0xFFFFFFFFu, pd, 1, 8);
            if ((lane & 7) == 0) {
                als[row * 4 + head] = ps;
                ald[row * 4 + head] = pd;
            }
        } else {
            const float4 as = ((const float4*)asrc)[lane];
            const float4 ad = ((const float4*)adst)[lane];
            ps = a.x * as.x + a.y * as.y + a.z * as.z + a.w * as.w;
            pd = a.x * ad.x + a.y * ad.y + a.z * ad.z + a.w * ad.w;
#pragma unroll
            for (int off = 16; off; off >>= 1) {
                ps += __shfl_down_sync(0xFFFFFFFFu, ps, off);
                pd += __shfl_down_sync(0xFFFFFFFFu, pd, off);
            }
            if (lane == 0) {
                als[row] = ps;
                ald[row] = pd;
            }
        }
    }
}

// ---------------- layer-1 attention aggregation (one warp per dst) ----------
__global__ void k_att1(const float* __restrict__ b1, int n) {
    int gw = (blockIdx.x * blockDim.x + threadIdx.x) >> 5;
    int lane = threadIdx.x & 31;
    if (gw >= n) return;
    int head = lane >> 3;
    float aldh = g_ald1[gw * 4 + head];

    float m = -1e30f, ssum = 0.f;
    float4 acc = make_float4(0.f, 0.f, 0.f, 0.f);
    int beg = g_rowptr[gw], end = g_rowptr[gw + 1];
    const float4* hv4 = (const float4*)g_h1;

    int s = (beg < end) ? __ldg(&g_col[beg]) : 0;
    for (int e = beg; e < end; e++) {
        int snext = (e + 1 < end) ? __ldg(&g_col[e + 1]) : 0;
        float ev = __ldg(&g_als1[s * 4 + head]) + aldh;
        ev = ev > 0.f ? ev : 0.2f * ev;                 // leaky relu
        float m2 = fmaxf(m, ev);
        float scale = __expf(m - m2);
        float wgt = __expf(ev - m2);
        ssum = ssum * scale + wgt;
        float4 h = __ldg(&hv4[s * 32 + lane]);
        acc.x = acc.x * scale + wgt * h.x;
        acc.y = acc.y * scale + wgt * h.y;
        acc.z = acc.z * scale + wgt * h.z;
        acc.w = acc.w * scale + wgt * h.w;
        m = m2;
        s = snext;
    }
    float inv = 1.f / (ssum + 1e-16f);
    float4 bb = ((const float4*)b1)[lane];
    float4 o;
    o.x = acc.x * inv + bb.x;
    o.y = acc.y * inv + bb.y;
    o.z = acc.z * inv + bb.z;
    o.w = acc.w * inv + bb.w;
    o.x = o.x > 0.f ? o.x : expm1f(o.x);
    o.y = o.y > 0.f ? o.y : expm1f(o.y);
    o.z = o.z > 0.f ? o.z : expm1f(o.z);
    o.w = o.w > 0.f ? o.w : expm1f(o.w);
    ((float4*)g_z)[gw * 32 + lane] = o;
}

// ---------------- layer-2 attention aggregation (heads=1, 128 ch) ----------
__global__ void k_att2(const float* __restrict__ b2, float* __restrict__ out, int n) {
    int gw = (blockIdx.x * blockDim.x + threadIdx.x) >> 5;
    int lane = threadIdx.x & 31;
    if (gw >= n) return;
    float aldh = g_ald2[gw];

    float m = -1e30f, ssum = 0.f;
    float4 acc = make_float4(0.f, 0.f, 0.f, 0.f);
    int beg = g_rowptr[gw], end = g_rowptr[gw + 1];
    const float4* hv4 = (const float4*)g_h2;

    int s = (beg < end) ? __ldg(&g_col[beg]) : 0;
    for (int e = beg; e < end; e++) {
        int snext = (e + 1 < end) ? __ldg(&g_col[e + 1]) : 0;
        float ev = __ldg(&g_als2[s]) + aldh;
        ev = ev > 0.f ? ev : 0.2f * ev;
        float m2 = fmaxf(m, ev);
        float scale = __expf(m - m2);
        float wgt = __expf(ev - m2);
        ssum = ssum * scale + wgt;
        float4 h = __ldg(&hv4[s * 32 + lane]);
        acc.x = acc.x * scale + wgt * h.x;
        acc.y = acc.y * scale + wgt * h.y;
        acc.z = acc.z * scale + wgt * h.z;
        acc.w = acc.w * scale + wgt * h.w;
        m = m2;
        s = snext;
    }
    float inv = 1.f / (ssum + 1e-16f);
    float4 bb = ((const float4*)b2)[lane];
    float4 o;
    o.x = acc.x * inv + bb.x;
    o.y = acc.y * inv + bb.y;
    o.z = acc.z * inv + bb.z;
    o.w = acc.w * inv + bb.w;
    ((float4*)out)[gw * 32 + lane] = o;
}

// ---------------- launch -----------------------------------------------------
extern "C" void kernel_launch(void* const* d_in, const int* in_sizes, int n_in,
                              void* d_out, int out_size) {
    const float* x  = (const float*)d_in[0];
    const void*  ei = d_in[1];
    const float* W1 = (const float*)d_in[2];
    const float* as1 = (const float*)d_in[3];
    const float* ad1 = (const float*)d_in[4];
    const float* b1 = (const float*)d_in[5];
    const float* W2 = (const float*)d_in[6];
    const float* as2 = (const float*)d_in[7];
    const float* ad2 = (const float*)d_in[8];
    const float* b2 = (const float*)d_in[9];
    float* out = (float*)d_out;

    int E = in_sizes[1] / 2;
    int n = in_sizes[0] / DIM;
    int tot = E + n;
    int nb = (n + SCAN_BLK - 1) / SCAN_BLK;

    k_detect<<<1, 256>>>((const unsigned int*)ei);
    k_zero<<<(n + 255) / 256, 256>>>(n);
    k_build<<<(tot + 255) / 256, 256>>>(ei, E, n);
    k_scan_a<<<nb, SCAN_BLK>>>(n);
    k_scan_b<<<1, 256>>>(nb, n);
    k_scan_c<<<nb, SCAN_BLK>>>(n);
    k_scatter<<<(tot + 255) / 256, 256>>>(tot);

    int gblocks = (n + 15) / 16;
    int ablocks = (n * 32 + 127) / 128;

    k_gemm<<<gblocks, 128>>>(x, W1, as1, ad1, 4, 1, n);
    k_att1<<<ablocks, 128>>>(b1, n);
    k_gemm<<<gblocks, 128>>>(x, W2, as2, ad2, 1, 2, n);
    k_att2<<<ablocks, 128>>>(b2, out, n);
}